// round 2
// baseline (speedup 1.0000x reference)
#include <cuda_runtime.h>
#include <cuda_bf16.h>

// Problem constants
#define T_STEPS 4
#define BATCH   64
#define CIN     64
#define COUT    128
#define HH      32
#define WW      32
#define TAU     0.5f
#define THRESH  1.0f
#define BN_EPS  1e-5f

// Scratch: transposed weights [cin*9][cout] + folded BN affine
__device__ float g_wT[CIN * 9 * COUT];
__device__ float g_alpha[COUT];
__device__ float g_beta[COUT];

// ---------- f32x2 packed helpers ----------
__device__ __forceinline__ unsigned long long pack2(float lo, float hi) {
    unsigned long long r;
    asm("mov.b64 %0, {%1, %2};" : "=l"(r) : "f"(lo), "f"(hi));
    return r;
}
__device__ __forceinline__ void unpack2(unsigned long long v, float& lo, float& hi) {
    asm("mov.b64 {%0, %1}, %2;" : "=f"(lo), "=f"(hi) : "l"(v));
}
__device__ __forceinline__ void ffma2(unsigned long long& d,
                                      unsigned long long a,
                                      unsigned long long b) {
    asm("fma.rn.f32x2 %0, %1, %2, %3;" : "=l"(d) : "l"(a), "l"(b), "l"(d));
}

// ---------- prep: weight transpose + BN fold ----------
__global__ void prep_kernel(const float* __restrict__ w,
                            const float* __restrict__ cb,
                            const float* __restrict__ gamma,
                            const float* __restrict__ beta,
                            const float* __restrict__ mean,
                            const float* __restrict__ var) {
    int idx = blockIdx.x * blockDim.x + threadIdx.x;
    int stride = gridDim.x * blockDim.x;
    // wT[r][co] = w[co][r], r = cin*9 + k (k = kh*3+kw)
    for (int i = idx; i < CIN * 9 * COUT; i += stride) {
        int co = i & (COUT - 1);
        int r  = i >> 7;           // / COUT
        g_wT[i] = w[co * (CIN * 9) + r];
    }
    if (idx < COUT) {
        float inv = rsqrtf(var[idx] + BN_EPS);
        float sc  = gamma[idx] * inv;
        g_alpha[idx] = sc;
        // y = (conv + b)*sc + (beta - mean*sc)  ->  conv*sc + (b*sc + beta - mean*sc)
        g_beta[idx] = beta[idx] - mean[idx] * sc + cb[idx] * sc;
    }
}

// ---------- fused conv3x3 + BN + LIF ----------
// Grid: (B, COUT/32, HH/8). Block: 256 threads.
// Thread tile: 8 couts (4 f32x2 pairs) x 4 pixels (1 row, 4 consecutive w).
#define CIN_CHUNK 16
#define SX_ROWS   10          // 8 + 2 halo
#define SX_PITCH  36          // 34 used, padded to mult-of-4 for LDS.128 alignment

__global__ __launch_bounds__(256, 2)
void conv_lif_kernel(const float* __restrict__ x, float* __restrict__ out) {
    __shared__ __align__(16) float sx[CIN_CHUNK * SX_ROWS * SX_PITCH]; // 23040 B
    __shared__ __align__(16) float sw[CIN_CHUNK * 9 * 32];             // 18432 B

    const int b     = blockIdx.x;
    const int cout0 = blockIdx.y * 32;
    const int h0    = blockIdx.z * 8;

    const int tid    = threadIdx.x;
    const int w_grp  = tid & 7;          // 8 groups of 4 w-pixels
    const int h_loc  = (tid >> 3) & 7;   // 8 rows
    const int co_grp = tid >> 6;         // 4 groups of 8 couts
    const int w0     = w_grp * 4;
    const int myc0   = cout0 + co_grp * 8;

    float alpha[8], betav[8];
#pragma unroll
    for (int i = 0; i < 8; i++) {
        alpha[i] = g_alpha[myc0 + i];
        betav[i] = g_beta[myc0 + i];
    }

    float mem[8][4];
#pragma unroll
    for (int c = 0; c < 8; c++)
#pragma unroll
        for (int p = 0; p < 4; p++) mem[c][p] = 0.f;

    for (int t = 0; t < T_STEPS; t++) {
        unsigned long long acc[4][4];
#pragma unroll
        for (int cp = 0; cp < 4; cp++)
#pragma unroll
            for (int p = 0; p < 4; p++) acc[cp][p] = 0ULL;

        for (int c0 = 0; c0 < CIN; c0 += CIN_CHUNK) {
            __syncthreads();  // previous chunk's smem reads complete

            // ---- load x tile (with halo, zero padded) ----
            const float* xb = x + (((t * BATCH + b) * CIN + c0) * (HH * WW));
            for (int e = tid; e < CIN_CHUNK * SX_ROWS * 34; e += 256) {
                int ci  = e / (SX_ROWS * 34);
                int rem = e - ci * (SX_ROWS * 34);
                int r   = rem / 34;
                int c   = rem - r * 34;
                int gh  = h0 - 1 + r;
                int gw  = c - 1;
                float v = 0.f;
                if ((unsigned)gh < (unsigned)HH && (unsigned)gw < (unsigned)WW)
                    v = xb[ci * (HH * WW) + gh * WW + gw];
                sx[ci * (SX_ROWS * SX_PITCH) + r * SX_PITCH + c] = v;
            }

            // ---- load weight tile (coalesced both sides) ----
            const float* wb = g_wT + c0 * 9 * COUT + cout0;
            for (int e = tid; e < CIN_CHUNK * 9 * 32; e += 256) {
                int co = e & 31;
                int rk = e >> 5;  // ci*9 + k
                sw[rk * 32 + co] = wb[rk * COUT + co];
            }
            __syncthreads();

            // ---- main accumulation ----
            for (int ci = 0; ci < CIN_CHUNK; ci++) {
#pragma unroll
                for (int kh = 0; kh < 3; kh++) {
                    const float* xr =
                        &sx[ci * (SX_ROWS * SX_PITCH) + (h_loc + kh) * SX_PITCH + w0];
                    float4 xa = *reinterpret_cast<const float4*>(xr);
                    float2 xc = *reinterpret_cast<const float2*>(xr + 4);
                    unsigned long long xd[6];
                    xd[0] = pack2(xa.x, xa.x);
                    xd[1] = pack2(xa.y, xa.y);
                    xd[2] = pack2(xa.z, xa.z);
                    xd[3] = pack2(xa.w, xa.w);
                    xd[4] = pack2(xc.x, xc.x);
                    xd[5] = pack2(xc.y, xc.y);
#pragma unroll
                    for (int kw = 0; kw < 3; kw++) {
                        const ulonglong2* wp = reinterpret_cast<const ulonglong2*>(
                            &sw[(ci * 9 + kh * 3 + kw) * 32 + co_grp * 8]);
                        ulonglong2 wA = wp[0];
                        ulonglong2 wB = wp[1];
                        unsigned long long wq0 = wA.x, wq1 = wA.y, wq2 = wB.x, wq3 = wB.y;
#pragma unroll
                        for (int p = 0; p < 4; p++) {
                            ffma2(acc[0][p], wq0, xd[kw + p]);
                            ffma2(acc[1][p], wq1, xd[kw + p]);
                            ffma2(acc[2][p], wq2, xd[kw + p]);
                            ffma2(acc[3][p], wq3, xd[kw + p]);
                        }
                    }
                }
            }
        }

        // ---- epilogue: BN affine + LIF update + spike store ----
        float* ob = out + ((size_t)(t * BATCH + b) * COUT) * (HH * WW)
                        + (h0 + h_loc) * WW + w0;
#pragma unroll
        for (int cp = 0; cp < 4; cp++) {
            const int cl0 = 2 * cp, cl1 = 2 * cp + 1;
            float4 s0, s1;
            float sp0[4], sp1[4];
#pragma unroll
            for (int p = 0; p < 4; p++) {
                float lo, hi;
                unpack2(acc[cp][p], lo, hi);
                float y0 = lo * alpha[cl0] + betav[cl0];
                float y1 = hi * alpha[cl1] + betav[cl1];
                float m0 = mem[cl0][p] * TAU + y0;
                float m1 = mem[cl1][p] * TAU + y1;
                float k0 = (m0 > THRESH) ? 1.f : 0.f;
                float k1 = (m1 > THRESH) ? 1.f : 0.f;
                mem[cl0][p] = (k0 != 0.f) ? 0.f : m0;  // hard reset
                mem[cl1][p] = (k1 != 0.f) ? 0.f : m1;
                sp0[p] = k0;
                sp1[p] = k1;
            }
            s0 = make_float4(sp0[0], sp0[1], sp0[2], sp0[3]);
            s1 = make_float4(sp1[0], sp1[1], sp1[2], sp1[3]);
            *reinterpret_cast<float4*>(ob + (size_t)(myc0 + cl0) * (HH * WW)) = s0;
            *reinterpret_cast<float4*>(ob + (size_t)(myc0 + cl1) * (HH * WW)) = s1;
        }
    }
}

extern "C" void kernel_launch(void* const* d_in, const int* in_sizes, int n_in,
                              void* d_out, int out_size) {
    (void)in_sizes; (void)n_in; (void)out_size;
    const float* x      = (const float*)d_in[0];
    const float* conv_w = (const float*)d_in[1];
    const float* conv_b = (const float*)d_in[2];
    const float* bng    = (const float*)d_in[3];
    const float* bnb    = (const float*)d_in[4];
    const float* bnm    = (const float*)d_in[5];
    const float* bnv    = (const float*)d_in[6];
    float* out = (float*)d_out;

    prep_kernel<<<72, 256>>>(conv_w, conv_b, bng, bnb, bnm, bnv);

    dim3 grid(BATCH, COUT / 32, HH / 8);
    conv_lif_kernel<<<grid, 256>>>(x, out);
}